// round 9
// baseline (speedup 1.0000x reference)
#include <cuda_runtime.h>
#include <math.h>

// Problem constants (fixed by setup_inputs)
#define B_  32
#define K_  16
#define T_  30
#define N_  128
#define n_  20
#define NN  (N_ * n_)        // 2560 nodes per batch
#define BK  (B_ * K_)        // 512
#define CHUNK0 128           // nodes pre-scanned in kernel 1

#define YAW_THRESH  1.0471975511965976f   // pi/3
#define INF_F       __int_as_float(0x7f800000)
#define INF_BITS    0x7f800000

// Global scratch (no allocations allowed): per-(t, bk) min cost (int-encoded
// nonnegative float: bit order == value order), straggler queue.
__device__ int g_minbits[32 * BK];      // [t][bk]
__device__ int g_queue[BK * T_];
__device__ int g_qcnt;                  // static-init 0; K3 resets after use

__device__ __forceinline__ float fast_sqrt(float x) {
    float r;
    asm("sqrt.approx.f32 %0, %1;" : "=f"(r) : "f"(x));
    return r;
}

// cost = relu(dist - 2) + relu(|wrap(yaw_n - yaw_p)| - pi/3); masked -> inf.
// yaw = -atan2(dx, dy) is a reflection of the direction angle, so
// |wrapped yaw diff| == angle(u, v) between raw direction vectors
// (segment starts / t = 0 map to direction (0, 1)).
// Exact-zero (no transcendentals): d2 <= 4 AND dot >= 0 AND cross^2 <= 3*dot^2
// (tan(pi/3)^2 == 3). Masked nodes use x = +inf -> d2 = inf: zero test fails,
// cost path yields +inf.

// ---------------------------------------------------------------------------
// Kernel 1: fast path. One block per (b, k); warps 0..29 <-> timesteps.
// Scan only the first 128 nodes (smem-cached once per block). Zero hit ->
// min finalized (cost >= 0). Miss -> record partial min, enqueue globally.
// Every block does near-constant small work -> no block-level stragglers.
// ---------------------------------------------------------------------------
__global__ __launch_bounds__(1024)
void k1_fastpath(const float* __restrict__ preds,
                 const float* __restrict__ cn,
                 const int*   __restrict__ mask) {
    const int bk = blockIdx.x;
    const int b  = bk >> 4;                 // / K_

    const float2* cnb = (const float2*)cn + (size_t)b * NN;
    const int*    mb  = mask + (size_t)b * NN;
    const float2* pp  = (const float2*)preds + (size_t)bk * T_;

    __shared__ float4 s_nd[CHUNK0];

    const int tid  = threadIdx.x;
    const int warp = tid >> 5;
    const int lane = tid & 31;

    if (tid < CHUNK0) {
        const int idx = tid;
        float2 p = cnb[idx];
        float2 q = cnb[idx > 0 ? idx - 1 : 0];
        int    m = mb[idx];
        bool start = (idx % n_ == 0);
        float ux = start ? 0.0f : p.x - q.x;
        float uy = start ? 1.0f : p.y - q.y;
        float x  = (m == 1) ? INF_F : p.x;   // masked -> d2 = +inf
        s_nd[idx] = make_float4(x, p.y, ux, uy);
    }
    __syncthreads();

    if (warp < T_) {
        const int t = warp;
        const float2 pt = pp[t];
        float vx = 0.0f, vy = 1.0f;          // yaw 0 <-> direction (0, 1)
        if (t != 0) {
            float2 pm = pp[t - 1];
            vx = pt.x - pm.x;
            vy = pt.y - pm.y;
        }

        float d2[4], dt[4], cr[4];
        bool anyzero = false;
        #pragma unroll
        for (int j = 0; j < 4; ++j) {
            float4 nd = s_nd[j * 32 + lane];
            float dx = nd.x - pt.x;
            float dy = nd.y - pt.y;
            d2[j] = fmaf(dx, dx, dy * dy);
            dt[j] = fmaf(nd.z, vx, nd.w * vy);    // dot(u, v)
            cr[j] = fmaf(nd.z, vy, -nd.w * vx);   // cross(u, v)
            anyzero |= (d2[j] <= 4.0f) && (dt[j] >= 0.0f) &&
                       (cr[j] * cr[j] <= 3.0f * dt[j] * dt[j]);
        }

        if (__ballot_sync(0xffffffffu, anyzero)) {
            if (lane == 0) g_minbits[t * BK + bk] = 0;
        } else {
            float lmin = INF_F;
            #pragma unroll
            for (int j = 0; j < 4; ++j) {
                float cd = (d2[j] <= 4.0f) ? 0.0f : (fast_sqrt(d2[j]) - 2.0f);
                float a  = atan2f(fabsf(cr[j]), dt[j]);
                lmin = fminf(lmin, cd + fmaxf(a - YAW_THRESH, 0.0f));
            }
            lmin = fminf(lmin, __shfl_xor_sync(0xffffffffu, lmin, 16));
            lmin = fminf(lmin, __shfl_xor_sync(0xffffffffu, lmin, 8));
            lmin = fminf(lmin, __shfl_xor_sync(0xffffffffu, lmin, 4));
            lmin = fminf(lmin, __shfl_xor_sync(0xffffffffu, lmin, 2));
            lmin = fminf(lmin, __shfl_xor_sync(0xffffffffu, lmin, 1));
            if (lane == 0) {
                g_minbits[t * BK + bk] = __float_as_int(lmin);
                int pos = atomicAdd(&g_qcnt, 1);
                g_queue[pos] = (bk << 5) | t;
            }
        }
    }
}

// ---------------------------------------------------------------------------
// Kernel 2: globally load-balanced stragglers. One block per queued (bk, t);
// 256 threads scan nodes [128, NN) (~10 each) and atomicMin the result.
// ---------------------------------------------------------------------------
__global__ __launch_bounds__(256)
void k2_stragglers(const float* __restrict__ preds,
                   const float* __restrict__ cn,
                   const int*   __restrict__ mask) {
    const int qcnt = g_qcnt;
    __shared__ float s_red[8];

    for (int item = blockIdx.x; item < qcnt; item += gridDim.x) {
        const int code = g_queue[item];
        const int bk = code >> 5;
        const int t  = code & 31;
        const int b  = bk >> 4;

        const float2* cnb = (const float2*)cn + (size_t)b * NN;
        const int*    mb  = mask + (size_t)b * NN;
        const float2* pp  = (const float2*)preds + (size_t)bk * T_;

        const float2 pt = pp[t];
        float vx = 0.0f, vy = 1.0f;
        if (t != 0) {
            float2 pm = pp[t - 1];
            vx = pt.x - pm.x;
            vy = pt.y - pm.y;
        }

        const int tid  = threadIdx.x;
        float lmin = INF_F;
        for (int idx = CHUNK0 + tid; idx < NN; idx += 256) {
            float2 p = cnb[idx];
            float2 q = cnb[idx - 1];
            int    m = mb[idx];
            bool start = (idx % n_ == 0);
            float ux = start ? 0.0f : p.x - q.x;
            float uy = start ? 1.0f : p.y - q.y;
            float x  = (m == 1) ? INF_F : p.x;

            float dx = x - pt.x;
            float dy = p.y - pt.y;
            float d2 = fmaf(dx, dx, dy * dy);
            float dt = fmaf(ux, vx, uy * vy);
            float cr = fmaf(ux, vy, -uy * vx);

            float c;
            if ((d2 <= 4.0f) && (dt >= 0.0f) && (cr * cr <= 3.0f * dt * dt)) {
                c = 0.0f;
            } else {
                float cd = (d2 <= 4.0f) ? 0.0f : (fast_sqrt(d2) - 2.0f);
                float a  = atan2f(fabsf(cr), dt);
                c = cd + fmaxf(a - YAW_THRESH, 0.0f);
            }
            lmin = fminf(lmin, c);
        }

        lmin = fminf(lmin, __shfl_xor_sync(0xffffffffu, lmin, 16));
        lmin = fminf(lmin, __shfl_xor_sync(0xffffffffu, lmin, 8));
        lmin = fminf(lmin, __shfl_xor_sync(0xffffffffu, lmin, 4));
        lmin = fminf(lmin, __shfl_xor_sync(0xffffffffu, lmin, 2));
        lmin = fminf(lmin, __shfl_xor_sync(0xffffffffu, lmin, 1));
        if ((tid & 31) == 0) s_red[tid >> 5] = lmin;
        __syncthreads();
        if (tid < 8) {
            float v = s_red[tid];
            v = fminf(v, __shfl_xor_sync(0xffu, v, 4));
            v = fminf(v, __shfl_xor_sync(0xffu, v, 2));
            v = fminf(v, __shfl_xor_sync(0xffu, v, 1));
            if (tid == 0)
                atomicMin(&g_minbits[t * BK + bk], __float_as_int(v));
        }
        __syncthreads();
    }
}

// ---------------------------------------------------------------------------
// Kernel 3: sum over T per (b, k) (coalesced over bk), reset queue counter.
// ---------------------------------------------------------------------------
__global__ __launch_bounds__(256)
void k3_reduce(float* __restrict__ out) {
    const int bk = blockIdx.x * 256 + threadIdx.x;
    float v = 0.0f;
    #pragma unroll
    for (int t = 0; t < T_; ++t)
        v += __int_as_float(g_minbits[t * BK + bk]);
    out[bk] = v;
    if (bk == 0) g_qcnt = 0;   // restore state for the next graph replay
}

extern "C" void kernel_launch(void* const* d_in, const int* in_sizes, int n_in,
                              void* d_out, int out_size) {
    const float* preds = (const float*)d_in[0];
    const float* cn    = (const float*)d_in[1];
    const int*   mask  = (const int*)d_in[2];
    float* out = (float*)d_out;

    k1_fastpath<<<BK, 1024>>>(preds, cn, mask);
    k2_stragglers<<<256, 256>>>(preds, cn, mask);
    k3_reduce<<<BK / 256, 256>>>(out);
}